// round 12
// baseline (speedup 1.0000x reference)
#include <cuda_runtime.h>
#include <cuda_fp16.h>
#include <cstdint>
#include <math.h>

#define GN_N_NODES 200000
#define GN_N_FEAT 256
#define NODES_PER_GEMV_BLOCK 32   // 8 warps x 4 nodes
#define MSG_THREADS 512
#define MSG_BLOCKS 148            // 74 clusters of 2 (148 = 2*74 packs perfectly)

// Scratch (device globals — zero-initialized BSS; no allocations allowed)
__device__ float  g_h[GN_N_NODES];      // x @ W
__device__ float  g_dis[GN_N_NODES];    // rsqrt(deg+1)
__device__ __half g_a[GN_N_NODES];      // fp16(dis * h) — gather source (400KB)
__device__ float  g_degacc[GN_N_NODES]; // edge-weight degree accumulator (kept zeroed)

// ---------------------------------------------------------------------------
// Inline per-block dtype detection (see earlier rounds for the argument).
// ---------------------------------------------------------------------------
__device__ __forceinline__ int detect_is64(const void* __restrict__ ei,
                                           int E, int N) {
    __shared__ int s;
    if (threadIdx.x < 32) {
        size_t stride = (size_t)(E / 32);
        long long v = ((const long long*)ei)[(size_t)threadIdx.x * stride];
        unsigned ok = __ballot_sync(0xFFFFFFFFu, v >= 0 && v < (long long)N);
        if (threadIdx.x == 0) s = (ok == 0xFFFFFFFFu) ? 1 : 0;
    }
    __syncthreads();
    return s;
}

// ---------------------------------------------------------------------------
// Fused kernel 1: GEMV blocks + degree-scatter blocks interleaved (Bresenham).
// (unchanged from R10 best)
// ---------------------------------------------------------------------------
__global__ void k_fused1(const float* __restrict__ x,
                         const float* __restrict__ W,
                         float* __restrict__ h,
                         float* __restrict__ degacc,
                         int n_nodes,
                         const void* __restrict__ ei,
                         const float* __restrict__ attrs,
                         int E,
                         int nb_gemv, int nb_total) {
    int is64 = detect_is64(ei, E, n_nodes);
    long long b = blockIdx.x;
    long long before = b * nb_gemv / nb_total;
    long long incl   = (b + 1) * nb_gemv / nb_total;
    if (incl > before) {
        int warp = threadIdx.x >> 5;
        int lane = threadIdx.x & 31;
        int node0 = (int)before * NODES_PER_GEMV_BLOCK + warp * 4;

        const float4* wv = reinterpret_cast<const float4*>(W);
        float4 b0 = __ldg(&wv[lane]);
        float4 b1 = __ldg(&wv[lane + 32]);

#pragma unroll
        for (int k = 0; k < 4; k++) {
            int node = node0 + k;
            if (node >= n_nodes) break;
            const float4* xr = reinterpret_cast<const float4*>(x + (size_t)node * GN_N_FEAT);
            float4 a0 = __ldcs(&xr[lane]);
            float4 a1 = __ldcs(&xr[lane + 32]);
            float s = a0.x * b0.x + a0.y * b0.y + a0.z * b0.z + a0.w * b0.w
                    + a1.x * b1.x + a1.y * b1.y + a1.z * b1.z + a1.w * b1.w;
#pragma unroll
            for (int o = 16; o; o >>= 1) s += __shfl_down_sync(0xFFFFFFFFu, s, o);
            if (lane == 0) h[node] = s;
        }
    } else {
        int did = (int)(b - before);
        long long e0 = ((long long)did * 256 + threadIdx.x) * 8;
        if (e0 >= E) return;
        if (e0 + 7 < E) {
            float4 w0 = __ldcs(reinterpret_cast<const float4*>(attrs + e0));
            float4 w1 = __ldcs(reinterpret_cast<const float4*>(attrs + e0 + 4));
            int c[8];
            if (is64) {
                const long long* p = (const long long*)ei + E;
#pragma unroll
                for (int j = 0; j < 4; j++) {
                    longlong2 cc = __ldcs(reinterpret_cast<const longlong2*>(p + e0 + 2 * j));
                    c[2 * j] = (int)cc.x; c[2 * j + 1] = (int)cc.y;
                }
            } else {
                const int* p = (const int*)ei + E;
                int4 ca = __ldcs(reinterpret_cast<const int4*>(p + e0));
                int4 cb = __ldcs(reinterpret_cast<const int4*>(p + e0 + 4));
                c[0] = ca.x; c[1] = ca.y; c[2] = ca.z; c[3] = ca.w;
                c[4] = cb.x; c[5] = cb.y; c[6] = cb.z; c[7] = cb.w;
            }
            atomicAdd(&degacc[c[0]], w0.x);
            atomicAdd(&degacc[c[1]], w0.y);
            atomicAdd(&degacc[c[2]], w0.z);
            atomicAdd(&degacc[c[3]], w0.w);
            atomicAdd(&degacc[c[4]], w1.x);
            atomicAdd(&degacc[c[5]], w1.y);
            atomicAdd(&degacc[c[6]], w1.z);
            atomicAdd(&degacc[c[7]], w1.w);
        } else {
            for (long long e = e0; e < E; e++) {
                int c = is64 ? (int)((const long long*)ei)[E + e]
                             : ((const int*)ei)[E + e];
                atomicAdd(&degacc[c], attrs[e]);
            }
        }
    }
}

// ---------------------------------------------------------------------------
// Kernel C (scalar — measured best): dis=rsqrt(deg+1); a=fp16(dis*h); out=0
// ---------------------------------------------------------------------------
__global__ void k_rsqrt(float* __restrict__ degacc,
                        float* __restrict__ dis,
                        const float* __restrict__ h,
                        __half* __restrict__ a,
                        float* __restrict__ out,
                        int n_nodes) {
    int i = blockIdx.x * blockDim.x + threadIdx.x;
    if (i < n_nodes) {
        float d = degacc[i] + 1.0f;
        degacc[i] = 0.0f;
        float di = rsqrtf(d);
        dis[i] = di;
        a[i]   = __float2half(di * h[i]);
        out[i] = 0.0f;
    }
}

// ---------------------------------------------------------------------------
// Kernel D (cluster version): a[] staged into 2-CTA distributed shared memory;
// gathers become LDS/DSMEM instead of L1tex wavefronts.
//   CTA rank holds a[rank*half_n .. rank*half_n+half_n) in its smem.
// ---------------------------------------------------------------------------
__device__ __forceinline__ float gather_cl(unsigned int smem_base, int half_n, int r) {
    unsigned int tgt = (unsigned int)(r >= half_n);
    unsigned int laddr = smem_base + (unsigned int)(r - (int)tgt * half_n) * 2u;
    unsigned int raddr;
    asm("mapa.shared::cluster.u32 %0, %1, %2;" : "=r"(raddr) : "r"(laddr), "r"(tgt));
    unsigned short v;
    asm("ld.shared::cluster.b16 %0, [%1];" : "=h"(v) : "r"(raddr));
    __half hv;
    *reinterpret_cast<unsigned short*>(&hv) = v;
    return __half2float(hv);
}

extern __shared__ __half s_a[];

__global__ void __launch_bounds__(MSG_THREADS, 1) __cluster_dims__(2, 1, 1)
k_msg_cl(const void* __restrict__ ei,
         const float* __restrict__ attrs,
         const __half* __restrict__ a,
         float* __restrict__ out,
         int E, int N, int half_n) {
    int is64 = detect_is64(ei, E, N);

    unsigned int rank;
    asm("mov.u32 %0, %%cluster_ctarank;" : "=r"(rank));

    // Stage this CTA's half of a[] into smem (vectorized, 16B chunks).
    int base = (int)rank * half_n;
    int cnt = N - base < half_n ? N - base : half_n;
    {
        const uint4* src = reinterpret_cast<const uint4*>(a + base);
        uint4* dst = reinterpret_cast<uint4*>(s_a);
        int nvec = cnt / 8;
        for (int i = threadIdx.x; i < nvec; i += blockDim.x) dst[i] = src[i];
        for (int i = nvec * 8 + threadIdx.x; i < cnt; i += blockDim.x) s_a[i] = a[base + i];
    }
    asm volatile("barrier.cluster.arrive.aligned;" ::: "memory");
    asm volatile("barrier.cluster.wait.aligned;" ::: "memory");

    unsigned int smem_base;
    asm("{ .reg .u64 t; cvta.to.shared.u64 t, %1; cvt.u32.u64 %0, t; }"
        : "=r"(smem_base) : "l"(s_a));

    long long tid = (long long)blockIdx.x * blockDim.x + threadIdx.x;
    long long nth = (long long)gridDim.x * blockDim.x;

    for (long long e0 = tid * 4; e0 < E; e0 += nth * 4) {
        if (e0 + 3 < E) {
            float4 w = __ldcs(reinterpret_cast<const float4*>(attrs + e0));
            int r0, r1, r2, r3, c0, c1, c2, c3;
            if (is64) {
                const long long* pr = (const long long*)ei;
                const long long* pc = pr + E;
                longlong2 ra = __ldcs(reinterpret_cast<const longlong2*>(pr + e0));
                longlong2 rb = __ldcs(reinterpret_cast<const longlong2*>(pr + e0 + 2));
                longlong2 ca = __ldcs(reinterpret_cast<const longlong2*>(pc + e0));
                longlong2 cb = __ldcs(reinterpret_cast<const longlong2*>(pc + e0 + 2));
                r0 = (int)ra.x; r1 = (int)ra.y; r2 = (int)rb.x; r3 = (int)rb.y;
                c0 = (int)ca.x; c1 = (int)ca.y; c2 = (int)cb.x; c3 = (int)cb.y;
            } else {
                const int* pr = (const int*)ei;
                const int* pc = pr + E;
                int4 r = __ldcs(reinterpret_cast<const int4*>(pr + e0));
                int4 c = __ldcs(reinterpret_cast<const int4*>(pc + e0));
                r0 = r.x; r1 = r.y; r2 = r.z; r3 = r.w;
                c0 = c.x; c1 = c.y; c2 = c.z; c3 = c.w;
            }
            float v0 = gather_cl(smem_base, half_n, r0) * w.x;
            float v1 = gather_cl(smem_base, half_n, r1) * w.y;
            float v2 = gather_cl(smem_base, half_n, r2) * w.z;
            float v3 = gather_cl(smem_base, half_n, r3) * w.w;
            atomicAdd(&out[c0], v0);
            atomicAdd(&out[c1], v1);
            atomicAdd(&out[c2], v2);
            atomicAdd(&out[c3], v3);
        } else {
            for (long long e = e0; e < E; e++) {
                int r, c;
                if (is64) {
                    r = (int)((const long long*)ei)[e];
                    c = (int)((const long long*)ei)[E + e];
                } else {
                    r = ((const int*)ei)[e];
                    c = ((const int*)ei)[E + e];
                }
                atomicAdd(&out[c], gather_cl(smem_base, half_n, r) * attrs[e]);
            }
        }
    }

    // Peer CTA may still be reading our smem — don't exit early.
    asm volatile("barrier.cluster.arrive.aligned;" ::: "memory");
    asm volatile("barrier.cluster.wait.aligned;" ::: "memory");
}

// ---------------------------------------------------------------------------
// Kernel E (scalar — measured best): out = Mish(dis*(out + dis*h) + b)
// ---------------------------------------------------------------------------
__global__ void k_finish(float* __restrict__ out,
                         const float* __restrict__ dis,
                         const float* __restrict__ h,
                         const float* __restrict__ b,
                         int n_nodes) {
    int i = blockIdx.x * blockDim.x + threadIdx.x;
    if (i < n_nodes) {
        float di = dis[i];
        float t = di * (out[i] + di * h[i]) + b[0];
        float sp = (t > 20.f) ? t : log1pf(expf(t));
        out[i] = t * tanhf(sp);
    }
}

extern "C" void kernel_launch(void* const* d_in, const int* in_sizes, int n_in,
                              void* d_out, int out_size) {
    // identify inputs by element count (descending: x > edge > attrs > W > b)
    int ix = 0, ie = 1, ia = 2, iw = 3, ib = 4;
    {
        long long best = -1;
        for (int i = 0; i < n_in; i++) if ((long long)in_sizes[i] > best) { best = in_sizes[i]; ix = i; }
        long long second = -1;
        for (int i = 0; i < n_in; i++) if (i != ix && (long long)in_sizes[i] > second) { second = in_sizes[i]; ie = i; }
        long long third = -1;
        for (int i = 0; i < n_in; i++) if (i != ix && i != ie && (long long)in_sizes[i] > third) { third = in_sizes[i]; ia = i; }
        long long fourth = -1;
        for (int i = 0; i < n_in; i++) if (i != ix && i != ie && i != ia && (long long)in_sizes[i] > fourth) { fourth = in_sizes[i]; iw = i; }
        for (int i = 0; i < n_in; i++) if (i != ix && i != ie && i != ia && i != iw) ib = i;
    }

    const float* x    = (const float*)d_in[ix];
    const void*  ei   = d_in[ie];
    const float* atts = (const float*)d_in[ia];
    const float* W    = (const float*)d_in[iw];
    const float* b    = (const float*)d_in[ib];
    float*       out  = (float*)d_out;

    const int E = in_sizes[ia];                 // 12.8M
    const int N = in_sizes[ix] / GN_N_FEAT;     // 200k

    float*  h;    cudaGetSymbolAddress((void**)&h,    g_h);
    float*  dis;  cudaGetSymbolAddress((void**)&dis,  g_dis);
    __half* a;    cudaGetSymbolAddress((void**)&a,    g_a);
    float*  dacc; cudaGetSymbolAddress((void**)&dacc, g_degacc);

    // 1: fused GEMV + degree scatter (interleaved; deg 8 edges/thread)
    {
        int nb_gemv = (N + NODES_PER_GEMV_BLOCK - 1) / NODES_PER_GEMV_BLOCK;
        int nb_deg  = (E + 2047) / 2048;
        int nb_total = nb_gemv + nb_deg;
        k_fused1<<<nb_total, 256>>>(x, W, h, dacc, N, ei, atts, E,
                                    nb_gemv, nb_total);
    }
    // 2: rsqrt + a = fp16(dis*h) + out init
    k_rsqrt<<<(N + 255) / 256, 256>>>(dacc, dis, h, a, out, N);

    // 3: edge messages — cluster kernel, a[] in distributed shared memory
    {
        int half_n = (N + 1) / 2;                       // 100000
        size_t smem_bytes = ((size_t)half_n * 2 + 15) & ~15ull;  // 200000 B
        cudaFuncSetAttribute(k_msg_cl,
                             cudaFuncAttributeMaxDynamicSharedMemorySize,
                             (int)smem_bytes);
        cudaFuncSetAttribute(k_msg_cl,
                             cudaFuncAttributeNonPortableClusterSizeAllowed, 1);

        cudaLaunchConfig_t cfg = {};
        cfg.gridDim  = dim3(MSG_BLOCKS, 1, 1);
        cfg.blockDim = dim3(MSG_THREADS, 1, 1);
        cfg.dynamicSmemBytes = smem_bytes;
        cfg.stream = 0;
        cudaLaunchAttribute at[1];
        at[0].id = cudaLaunchAttributeClusterDimension;
        at[0].val.clusterDim.x = 2;
        at[0].val.clusterDim.y = 1;
        at[0].val.clusterDim.z = 1;
        cfg.attrs = at;
        cfg.numAttrs = 1;
        cudaLaunchKernelEx(&cfg, k_msg_cl,
                           (const void*)ei, (const float*)atts,
                           (const __half*)a, (float*)out, E, N, half_n);
    }
    // 4: scale + self loop + bias + Mish
    k_finish<<<(N + 255) / 256, 256>>>(out, dis, h, b, N);
}